// round 13
// baseline (speedup 1.0000x reference)
#include <cuda_runtime.h>
#include <math.h>

// Problem constants (fixed by setup_inputs)
#define B 4
#define H 320
#define W 320
#define NPIX   (B * H * W)
#define BPI    37                     // blocks per image: 4*37 = 148 = #SMs
#define NBLOCKS (B * BPI)             // 148 -> exactly one block per SM
#define TILE_MAX 9                    // max rows per block (320/37 -> 8 or 9)
#define HALO   8                      // staged halo (R10/R12 bench-proven)
#define NSTAGE (TILE_MAX + 2 * HALO)  // 25 staged rows -> 25-bit column mask
#define LAMBDA 1.0f

__device__ float g_accf;              // f32 accumulator (RED.ADD, validated)
__device__ unsigned int g_count;

// ---------------------------------------------------------------------------
// R10/R12 kernel (bench 8.6-8.8us x3) with ONE controlled change: the grid
// is balanced to 148 blocks (one per SM). Each image's 320 rows split over
// 37 blocks via the exact partition floor(i*320/37) -> 8 or 9 rows/block,
// eliminating the 12 double-loaded SMs of the grid=160 layout.
// Staging window is fixed at 25 rows (clamped to the image), which only ever
// adds REAL same-image rows to the seed mask -> vertical resolve stays exact.
//  1. 25-bit column seed mask from 25 batched coalesced LDG; pure-ALU
//     vertical resolve (clz/ffs); exact fallback if mask empty (P ~ 1e-7).
//  2. g2 -> smem, ONE barrier, pruned horizontal searches per thread.
//  3. Block reduce; RED.ADD.F32 + fence + counter; last block writes the
//     mean and resets globals (graph-replay safe).
// ---------------------------------------------------------------------------
__global__ void __launch_bounds__(W)
edt_tile_loss_kernel(const float* __restrict__ logits,
                     const int*   __restrict__ targets,
                     float*       __restrict__ out)
{
    __shared__ float s_g2[TILE_MAX][W];
    __shared__ float warp_sums[W / 32];

    const int blk   = blockIdx.x;            // 0 .. 147
    const int b     = blk / BPI;             // image
    const int bi    = blk - b * BPI;         // block within image, 0..36
    const int h0    = (bi * H) / BPI;        // first row (exact partition)
    const int hend  = ((bi + 1) * H) / BPI;  // one past last row
    const int nrows = hend - h0;             // 8 or 9
    const int wo    = threadIdx.x;           // column
    const size_t img_base = (size_t)b * H * W;

    const int*   tcol = targets + img_base + wo;
    const float* lcol = logits  + img_base + wo;

    // --- logits for my rows (independent, issue early; guarded) ---
    float xv[TILE_MAX];
    #pragma unroll
    for (int j = 0; j < TILE_MAX; ++j)
        xv[j] = (j < nrows) ? lcol[(h0 + j) * W] : 0.0f;

    // --- build 25-bit column seed mask (rows h0-HALO .. h0+TILE_MAX+HALO-1,
    //     clamped to this image: only real rows contribute) ---
    unsigned int mask = 0u;
    #pragma unroll
    for (int r = 0; r < NSTAGE; ++r) {
        const int hh = h0 - HALO + r;
        int v = 0;
        if (hh >= 0 && hh < H) v = tcol[hh * W];
        mask |= (unsigned int)(v != 0) << r;
    }

    // --- vertical resolve per pixel (pure ALU) ---
    #pragma unroll
    for (int j = 0; j < TILE_MAX; ++j) {
        if (j < nrows) {
            const int c = j + HALO;                   // staged index of pixel row
            const unsigned int below = mask & ((1u << (c + 1)) - 1u);  // <= c
            const unsigned int above = mask >> c;                      // >= c
            int d_up = 1 << 20, d_dn = 1 << 20;
            if (below) d_up = c - (31 - __clz(below));
            if (above) d_dn = __ffs(above) - 1;
            int v = min(d_up, d_dn);
            float g2;
            if (mask != 0u) {
                g2 = (float)(v * v);
            } else {
                // Exact fallback: no seed in the staged window (rare).
                const int h = h0 + j;
                g2 = INFINITY;
                for (int r = HALO + 1; r < H; ++r) {
                    const int hu = h - r, hd = h + r;
                    bool found = false;
                    if (hu >= 0 && tcol[hu * W] != 0) found = true;
                    if (hd < H  && tcol[hd * W] != 0) found = true;
                    if (found) { g2 = (float)(r * r); break; }
                }
            }
            s_g2[j][wo] = g2;
        }
    }
    __syncthreads();

    // --- horizontal pruned search + fused loss for my rows ---
    float acc = 0.0f;
    #pragma unroll
    for (int j = 0; j < TILE_MAX; ++j) {
        if (j < nrows) {
            const float* s = s_g2[j];
            float best = s[wo];
            for (int r = 1; r < W; ++r) {
                const float rr = (float)(r * r);
                if (rr >= best) break;
                const int lo = wo - r;
                const int hi = wo + r;
                if (lo >= 0) best = fminf(best, s[lo] + rr);
                if (hi < W)  best = fminf(best, s[hi] + rr);
            }
            const float d = sqrtf(best);
            const float p = 1.0f / (1.0f + __expf(-xv[j]));
            acc += p * d + LAMBDA * (1.0f - p);
        }
    }

    // --- block reduce + global accumulate (RED.ADD tail) ---
    #pragma unroll
    for (int off = 16; off > 0; off >>= 1)
        acc += __shfl_down_sync(0xFFFFFFFFu, acc, off);

    const int lane = wo & 31;
    const int wid  = wo >> 5;
    if (lane == 0) warp_sums[wid] = acc;
    __syncthreads();

    if (wid == 0 && lane == 0) {
        float v = 0.0f;
        #pragma unroll
        for (int i = 0; i < W / 32; ++i) v += warp_sums[i];
        atomicAdd(&g_accf, v);          // result unused -> REDG.ADD.F32
        __threadfence();                // my RED visible before counter bump
        const unsigned int done = atomicAdd(&g_count, 1u);
        if (done == NBLOCKS - 1) {
            float total;
            asm volatile("ld.global.cg.f32 %0, [%1];"
                         : "=f"(total) : "l"(&g_accf));
            out[0] = total / (float)NPIX;
            g_accf  = 0.0f;             // reset for next graph replay
            g_count = 0u;
        }
    }
}

extern "C" void kernel_launch(void* const* d_in, const int* in_sizes, int n_in,
                              void* d_out, int out_size)
{
    const float* logits  = (const float*)d_in[0];
    const int*   targets = (const int*)d_in[1];
    float*       out     = (float*)d_out;

    (void)in_sizes; (void)n_in; (void)out_size;

    edt_tile_loss_kernel<<<NBLOCKS, W>>>(logits, targets, out);
}

// round 14
// speedup vs baseline: 1.2913x; 1.2913x over previous
#include <cuda_runtime.h>
#include <math.h>

// Problem constants (fixed by setup_inputs)
#define B 4
#define H 320
#define W 320
#define NPIX   (B * H * W)
#define TILE   8                      // rows per block (champion shape, 3x benched)
#define HALO   8                      // staged halo above/below (champion shape)
#define NSTAGE (TILE + 2 * HALO)      // 24 staged rows -> 24-bit column mask
#define NBLOCKS (B * H / TILE)        // 160
#define LAMBDA 1.0f

__device__ float g_accf;              // f32 accumulator (RED.ADD, validated)
__device__ unsigned int g_count;

// ---------------------------------------------------------------------------
// Champion R10/R12 kernel (8.64/8.67us) with ONE micro-change in phase 2:
// the horizontal search uses CLAMPED indices instead of boundary branches.
// Exactness: a clamped term s[clamp(wo+-r)] + r^2 is always >= the true
// candidate value of that (valid) column, which is itself visited at its
// own radius -> the min is unchanged. r=1..3 peeled as straight-line code.
//
//  1. 24-bit column seed mask from 24 batched coalesced LDG; pure-ALU
//     vertical resolve (clz/ffs) for all 8 pixels; exact fallback if the
//     mask is empty (P ~ 1e-5).
//  2. g2 -> smem, ONE barrier, branchless-boundary pruned horizontal search.
//  3. Block reduce; RED.ADD.F32 + fence + counter; last block writes the
//     mean and resets globals (graph-replay safe).
// ---------------------------------------------------------------------------
__global__ void __launch_bounds__(W)
edt_tile_loss_kernel(const float* __restrict__ logits,
                     const int*   __restrict__ targets,
                     float*       __restrict__ out)
{
    __shared__ float s_g2[TILE][W];
    __shared__ float warp_sums[W / 32];

    const int tile = blockIdx.x;            // 0 .. NBLOCKS-1
    const int b    = tile / (H / TILE);
    const int h0   = (tile % (H / TILE)) * TILE;   // first row of strip
    const int wo   = threadIdx.x;                  // column
    const size_t img_base = (size_t)b * H * W;

    const int*   tcol = targets + img_base + wo;
    const float* lcol = logits  + img_base + wo;

    // --- logits for my 8 pixels (independent, issue early) ---
    float xv[TILE];
    #pragma unroll
    for (int j = 0; j < TILE; ++j)
        xv[j] = lcol[(h0 + j) * W];

    // --- build 24-bit column seed mask (rows h0-HALO .. h0+TILE+HALO-1) ---
    unsigned int mask = 0u;
    #pragma unroll
    for (int r = 0; r < NSTAGE; ++r) {
        const int hh = h0 - HALO + r;
        int v = 0;
        if (hh >= 0 && hh < H) v = tcol[hh * W];
        mask |= (unsigned int)(v != 0) << r;
    }

    // --- vertical resolve per pixel (pure ALU) ---
    #pragma unroll
    for (int j = 0; j < TILE; ++j) {
        const int c = j + HALO;                       // staged index of pixel row
        const unsigned int below = mask & ((1u << (c + 1)) - 1u);  // bits <= c
        const unsigned int above = mask >> c;                      // bits >= c
        int d_up = 1 << 20, d_dn = 1 << 20;
        if (below) d_up = c - (31 - __clz(below));
        if (above) d_dn = __ffs(above) - 1;
        int v = min(d_up, d_dn);
        float g2;
        if (mask != 0u) {
            g2 = (float)(v * v);
        } else {
            // Fallback: no seed in the staged window (astronomically rare).
            const int h = h0 + j;
            g2 = INFINITY;
            for (int r = HALO + 1; r < H; ++r) {
                const int hu = h - r, hd = h + r;
                bool found = false;
                if (hu >= 0 && tcol[hu * W] != 0) found = true;
                if (hd < H  && tcol[hd * W] != 0) found = true;
                if (found) { g2 = (float)(r * r); break; }
            }
        }
        s_g2[j][wo] = g2;
    }
    __syncthreads();

    // --- horizontal pruned search (branchless boundaries) + fused loss ---
    float acc = 0.0f;
    #pragma unroll
    for (int j = 0; j < TILE; ++j) {
        const float* s = s_g2[j];
        float best = s[wo];
        // Peel r=1..3 straight-line (clamped indices, exact per header note)
        #pragma unroll
        for (int r = 1; r <= 3; ++r) {
            const float rr = (float)(r * r);
            const int lo = max(wo - r, 0);
            const int hi = min(wo + r, W - 1);
            best = fminf(best, s[lo] + rr);
            best = fminf(best, s[hi] + rr);
        }
        for (int r = 4; r < W; ++r) {
            const float rr = (float)(r * r);
            if (rr >= best) break;
            const int lo = max(wo - r, 0);
            const int hi = min(wo + r, W - 1);
            best = fminf(best, s[lo] + rr);
            best = fminf(best, s[hi] + rr);
        }
        const float d = sqrtf(best);
        const float p = 1.0f / (1.0f + __expf(-xv[j]));
        acc += p * d + LAMBDA * (1.0f - p);
    }

    // --- block reduce + global accumulate (RED.ADD tail) ---
    #pragma unroll
    for (int off = 16; off > 0; off >>= 1)
        acc += __shfl_down_sync(0xFFFFFFFFu, acc, off);

    const int lane = wo & 31;
    const int wid  = wo >> 5;
    if (lane == 0) warp_sums[wid] = acc;
    __syncthreads();

    if (wid == 0 && lane == 0) {
        float v = 0.0f;
        #pragma unroll
        for (int i = 0; i < W / 32; ++i) v += warp_sums[i];
        atomicAdd(&g_accf, v);          // result unused -> REDG.ADD.F32
        __threadfence();                // my RED visible before counter bump
        const unsigned int done = atomicAdd(&g_count, 1u);
        if (done == NBLOCKS - 1) {
            float total;
            asm volatile("ld.global.cg.f32 %0, [%1];"
                         : "=f"(total) : "l"(&g_accf));
            out[0] = total / (float)NPIX;
            g_accf  = 0.0f;             // reset for next graph replay
            g_count = 0u;
        }
    }
}

extern "C" void kernel_launch(void* const* d_in, const int* in_sizes, int n_in,
                              void* d_out, int out_size)
{
    const float* logits  = (const float*)d_in[0];
    const int*   targets = (const int*)d_in[1];
    float*       out     = (float*)d_out;

    (void)in_sizes; (void)n_in; (void)out_size;

    edt_tile_loss_kernel<<<NBLOCKS, W>>>(logits, targets, out);
}